// round 7
// baseline (speedup 1.0000x reference)
#include <cuda_runtime.h>
#include <cuda_bf16.h>
#include <cstdint>

// B=4, N=256, OBS=40, ACT=8, HEAD=8, DIM=32, T=256
// Algebra: nh/hid independent of broadcast index -> only column sums S_n,S_h;
// final gather at tgt -> ah needed at 4 rows only.
// GEMMs on tensor cores: bf16 2-term split (h+l), 3 mma per product, fp32 accum.
// All GEMMs K=256: block 32x32 tile, 4 warps split K (64 each), smem phase-reduce.

#define KPAD 72   // 64 data halves + 8 pad; row stride 144B -> ldmatrix conflict-free

__device__ __align__(256) __nv_bfloat16 g_E1h[1024*256], g_E1l[1024*256];
__device__ __align__(256) __nv_bfloat16 g_We2Th[256*256], g_We2Tl[256*256];
__device__ __align__(256) __nv_bfloat16 g_WnTh[256*256],  g_WnTl[256*256];
__device__ __align__(256) __nv_bfloat16 g_WhTh[256*256],  g_WhTl[256*256];
__device__ __align__(256) __nv_bfloat16 g_adjh[256*256],  g_adjl[256*256];
__device__ __align__(256) __nv_bfloat16 g_E2fTh[4*256*256], g_E2fTl[4*256*256];
__device__ __align__(256) __nv_bfloat16 g_NEfh[1024*256], g_NEfl[1024*256];
__device__ float g_Sn[1024], g_Sh[1024], g_AH[1024];

__device__ __forceinline__ void bsplit(float v, __nv_bfloat16* ph, __nv_bfloat16* pl) {
    __nv_bfloat16 h = __float2bfloat16(v);
    *ph = h;
    *pl = __float2bfloat16(v - __bfloat162float(h));
}

__device__ __forceinline__ void cp16(uint32_t dst, const void* src) {
    asm volatile("cp.async.ca.shared.global [%0], [%1], 16;\n" :: "r"(dst), "l"(src));
}
__device__ __forceinline__ void ldm_x4(uint32_t* r, uint32_t addr) {
    asm volatile("ldmatrix.sync.aligned.m8n8.x4.shared.b16 {%0,%1,%2,%3}, [%4];"
                 : "=r"(r[0]), "=r"(r[1]), "=r"(r[2]), "=r"(r[3]) : "r"(addr));
}
__device__ __forceinline__ void mma_bf16(float* d, const uint32_t* a, uint32_t b0, uint32_t b1) {
    asm volatile("mma.sync.aligned.m16n8k16.row.col.f32.bf16.bf16.f32 "
                 "{%0,%1,%2,%3}, {%4,%5,%6,%7}, {%8,%9}, {%0,%1,%2,%3};"
                 : "+f"(d[0]), "+f"(d[1]), "+f"(d[2]), "+f"(d[3])
                 : "r"(a[0]), "r"(a[1]), "r"(a[2]), "r"(a[3]), "r"(b0), "r"(b1));
}

// ---------------------------------------------------------------------------
// K1: E1 = relu(obs@We1+be1) -> bf16 h/l. Block 0 zeroes accumulators.
__global__ void k_embed1(const float* __restrict__ x, const float* __restrict__ We1,
                         const float* __restrict__ be1) {
    __shared__ float xs[4][40];
    int r0 = blockIdx.x * 4;
    int tid = threadIdx.x;
    if (blockIdx.x == 0) {
#pragma unroll
        for (int i = 0; i < 4; i++) {
            g_Sn[i * 256 + tid] = 0.f;
            g_Sh[i * 256 + tid] = 0.f;
            g_AH[i * 256 + tid] = 0.f;
        }
    }
    if (tid < 160) {
        int rr = tid / 40, k = tid % 40;
        int row = r0 + rr;
        int b = row >> 8, i = row & 255;
        xs[rr][k] = x[b * 257 * 40 + i * 40 + k];
    }
    __syncthreads();
    float bias = be1[tid];
    float acc[4] = {bias, bias, bias, bias};
#pragma unroll
    for (int k = 0; k < 40; k++) {
        float w = We1[k * 256 + tid];
#pragma unroll
        for (int rr = 0; rr < 4; rr++) acc[rr] += xs[rr][k] * w;
    }
#pragma unroll
    for (int rr = 0; rr < 4; rr++) {
        float v = fmaxf(acc[rr], 0.f);
        size_t o = (size_t)(r0 + rr) * 256 + tid;
        bsplit(v, &g_E1h[o], &g_E1l[o]);
    }
}

// ---------------------------------------------------------------------------
// Convert weights to bf16 h/l. z=0..2: We2/Wn/Wh -> TRANSPOSED [n][k]; z=3: adj direct.
__global__ void k_convW(const float* __restrict__ We2, const float* __restrict__ Wn,
                        const float* __restrict__ Wh, const float* __restrict__ adj) {
    __shared__ float ts[32][33];
    int z = blockIdx.z;
    int tx = threadIdx.x, ty = threadIdx.y;
    int n0 = blockIdx.x * 32, k0 = blockIdx.y * 32;
    const float* in = (z == 0) ? We2 : (z == 1) ? Wn : (z == 2) ? Wh : adj;
    __nv_bfloat16* oh = (z == 0) ? g_We2Th : (z == 1) ? g_WnTh : (z == 2) ? g_WhTh : g_adjh;
    __nv_bfloat16* ol = (z == 0) ? g_We2Tl : (z == 1) ? g_WnTl : (z == 2) ? g_WhTl : g_adjl;
    if (z < 3) {
        for (int r = ty; r < 32; r += 8)
            ts[r][tx] = in[(size_t)(k0 + r) * 256 + n0 + tx];
        __syncthreads();
        for (int r = ty; r < 32; r += 8) {
            float v = ts[tx][r];   // = in[k0+tx][n0+r]
            size_t o = (size_t)(n0 + r) * 256 + k0 + tx;
            bsplit(v, &oh[o], &ol[o]);
        }
    } else {
        for (int r = ty; r < 32; r += 8) {
            size_t o = (size_t)(k0 + r) * 256 + n0 + tx;
            bsplit(in[o], &oh[o], &ol[o]);
        }
    }
}

// ---------------------------------------------------------------------------
// Tensor GEMM, C[32x32] = A[32x256] @ B[256x32], bf16 split, warp-split-K.
// MODE 0: E2 = E1@We2 -> relu(+be2) -> E2fT (transposed, split) per batch
// MODE 1: NE = adj@E2fT[b] -> NEf (split)            (grid.z = batch)
// MODE 2: colsum of relu(NEf@W + bias) -> Sn/Sh      (which selects Wn/Wh)
template <int MODE>
__global__ void __launch_bounds__(128) k_mma(const float* __restrict__ bias, int which) {
    __shared__ __align__(16) __nv_bfloat16 sm[2][4][32][KPAD]; // [stage][Ah,Al,Bh,Bl][row][k]
    __shared__ float red[32][33];
    int tid = threadIdx.x, lane = tid & 31, wid = tid >> 5;
    int row0 = blockIdx.y * 32, col0 = blockIdx.x * 32;

    const __nv_bfloat16 *pAh, *pAl, *pBh, *pBl;
    size_t aOff = (size_t)row0 * 256, bOff = (size_t)col0 * 256;
    if (MODE == 0) { pAh = g_E1h;  pAl = g_E1l;  pBh = g_We2Th; pBl = g_We2Tl; }
    if (MODE == 1) { pAh = g_adjh; pAl = g_adjl; pBh = g_E2fTh; pBl = g_E2fTl;
                     bOff += (size_t)blockIdx.z * 65536; }
    if (MODE == 2) { pAh = g_NEfh; pAl = g_NEfl;
                     pBh = which ? g_WhTh : g_WnTh; pBl = which ? g_WhTl : g_WnTl; }

    // warp w loads array w; lane = row; 8 x 16B per 64-half chunk
    const __nv_bfloat16* gsrc =
        ((wid == 0) ? pAh + aOff : (wid == 1) ? pAl + aOff
                    : (wid == 2) ? pBh + bOff : pBl + bOff) + (size_t)lane * 256;
    uint32_t smBase = (uint32_t)__cvta_generic_to_shared(&sm[0][0][0][0]);
    const uint32_t stageBytes = 4 * 32 * KPAD * 2;
    uint32_t myDst = smBase + (uint32_t)((wid * 32 + lane) * KPAD) * 2;

#define LOAD_CHUNK(c, st)                                                      \
    {                                                                          \
        const __nv_bfloat16* _s = gsrc + (c) * 64;                             \
        uint32_t _d = myDst + (st) * stageBytes;                               \
        _Pragma("unroll")                                                      \
        for (int i = 0; i < 8; i++) cp16(_d + i * 16, _s + i * 8);             \
        asm volatile("cp.async.commit_group;\n" ::);                           \
    }

    LOAD_CHUNK(0, 0)

    // ldmatrix lane address components
    int aRow = lane & 15;
    int aColSel = (lane >> 4) << 3;          // +8 for lanes 16-31
    int bRowSel = ((lane >> 4) << 3) + (lane & 7);
    int bColSel = lane & 8;

    float acc[2][4][4] = {};
    for (int c = 0; c < 4; c++) {
        if (c < 3) {
            LOAD_CHUNK(c + 1, (c + 1) & 1)
            asm volatile("cp.async.wait_group 1;\n" ::);
        } else {
            asm volatile("cp.async.wait_group 0;\n" ::);
        }
        __syncthreads();
        int st = c & 1;
        uint32_t stB = smBase + st * stageBytes;
        int kBase = wid * 16;   // warp's k16 within the 64-chunk
        uint32_t aAddr = stB + (uint32_t)((aRow)*KPAD + kBase + aColSel) * 2;
        uint32_t bAddr = stB + (uint32_t)((2 * 32 + bRowSel) * KPAD + kBase + bColSel) * 2;
        const uint32_t arrB = 32 * KPAD * 2;
        uint32_t ah0[4], ah1[4], al0[4], al1[4];
        uint32_t bh0[4], bh1[4], bl0[4], bl1[4];
        ldm_x4(ah0, aAddr);                       // Ah, m rows 0-15
        ldm_x4(ah1, aAddr + 16 * KPAD * 2);       // Ah, m rows 16-31
        ldm_x4(al0, aAddr + arrB);                // Al
        ldm_x4(al1, aAddr + arrB + 16 * KPAD * 2);
        ldm_x4(bh0, bAddr);                       // Bh, n 0-15 (atoms 0,1)
        ldm_x4(bh1, bAddr + 16 * KPAD * 2);       // Bh, n 16-31 (atoms 2,3)
        ldm_x4(bl0, bAddr + arrB);                // Bl
        ldm_x4(bl1, bAddr + arrB + 16 * KPAD * 2);
#pragma unroll
        for (int mi = 0; mi < 2; mi++) {
            const uint32_t* AH = mi ? ah1 : ah0;
            const uint32_t* AL = mi ? al1 : al0;
#pragma unroll
            for (int ni = 0; ni < 4; ni++) {
                const uint32_t* BH = (ni < 2) ? bh0 : bh1;
                const uint32_t* BL = (ni < 2) ? bl0 : bl1;
                int o = (ni & 1) * 2;
                float* d = acc[mi][ni];
                mma_bf16(d, AH, BH[o], BH[o + 1]);
                mma_bf16(d, AH, BL[o], BL[o + 1]);
                mma_bf16(d, AL, BH[o], BH[o + 1]);
            }
        }
        __syncthreads();
    }

    // phase-reduce the 4 warps' K-partials into red[32][33]
    int g = lane >> 2, t2 = (lane & 3) * 2;
    for (int w = 0; w < 4; w++) {
        if (wid == w) {
#pragma unroll
            for (int mi = 0; mi < 2; mi++)
#pragma unroll
                for (int ni = 0; ni < 4; ni++)
#pragma unroll
                    for (int r = 0; r < 4; r++) {
                        int row = mi * 16 + g + ((r >> 1) << 3);
                        int col = ni * 8 + t2 + (r & 1);
                        if (w == 0) red[row][col] = acc[mi][ni][r];
                        else        red[row][col] += acc[mi][ni][r];
                    }
        }
        __syncthreads();
    }

    if (MODE == 0) {
        int b = row0 >> 8, i0 = row0 & 255;
        for (int idx = tid; idx < 1024; idx += 128) {
            int r = idx & 31, cc = idx >> 5;
            float v = fmaxf(red[r][cc] + bias[col0 + cc], 0.f);
            size_t o = (size_t)b * 65536 + (size_t)(col0 + cc) * 256 + i0 + r;
            bsplit(v, &g_E2fTh[o], &g_E2fTl[o]);
        }
    }
    if (MODE == 1) {
        int b = blockIdx.z;
        for (int idx = tid; idx < 1024; idx += 128) {
            int cc = idx & 31, r = idx >> 5;
            size_t o = (size_t)(b * 256 + row0 + r) * 256 + col0 + cc;
            bsplit(red[r][cc], &g_NEfh[o], &g_NEfl[o]);
        }
    }
    if (MODE == 2) {
        if (tid < 32) {
            float bv = bias[col0 + tid];
            float s = 0.f;
#pragma unroll 8
            for (int r = 0; r < 32; r++) s += fmaxf(red[r][tid] + bv, 0.f);
            float* S = which ? g_Sh : g_Sn;
            atomicAdd(&S[(row0 >> 8) * 256 + col0 + tid], s);
        }
    }
#undef LOAD_CHUNK
}

// ---------------------------------------------------------------------------
// ah split-K partials: E2f[b,tgt,:] . Wl[:,t] in fp32. grid 16 (4b x 4 ksegs).
__global__ void k_ah(const float* __restrict__ x, const float* __restrict__ Wl) {
    __shared__ float vs[64];
    int b = blockIdx.x >> 2, kseg = blockIdx.x & 3;
    int t = threadIdx.x;
    int tgt = (int)x[b * 257 * 40 + 256 * 40];
    if (t < 64) {
        size_t o = (size_t)b * 65536 + (size_t)(kseg * 64 + t) * 256 + tgt;
        vs[t] = __bfloat162float(g_E2fTh[o]) + __bfloat162float(g_E2fTl[o]);
    }
    __syncthreads();
    float acc = 0.f;
#pragma unroll 8
    for (int k = 0; k < 64; k++)
        acc += vs[k] * Wl[(kseg * 64 + k) * 256 + t];
    atomicAdd(&g_AH[b * 256 + t], acc);
}

// ---------------------------------------------------------------------------
__global__ void k_final(const float* __restrict__ bl, const float* __restrict__ Wa,
                        const float* __restrict__ ba, float* __restrict__ out) {
    __shared__ float od[32];
    int b = blockIdx.x, tid = threadIdx.x;
    int h = tid >> 5, d = tid & 31;
    int t = d * 8 + h;
    float ahv = fmaxf(g_AH[b * 256 + t] + bl[t], 0.f);
    float logit = ahv * g_Sn[b * 256 + t];
    float m = logit;
#pragma unroll
    for (int o = 16; o > 0; o >>= 1) m = fmaxf(m, __shfl_xor_sync(0xffffffffu, m, o));
    float e = expf(logit - m);
    float ssum = e;
#pragma unroll
    for (int o = 16; o > 0; o >>= 1) ssum += __shfl_xor_sync(0xffffffffu, ssum, o);
    float val = (e / ssum) * g_Sh[b * 256 + t] * 0.125f;
    if (tid < 32) od[tid] = 0.f;
    __syncthreads();
    atomicAdd(&od[d], val);
    __syncthreads();
    if (tid < 8) {
        float acc = ba[tid];
#pragma unroll
        for (int dd = 0; dd < 32; dd++) acc += od[dd] * Wa[dd * 8 + tid];
        out[b * 8 + tid] = acc;
    }
    (void)h;
}

// ---------------------------------------------------------------------------
extern "C" void kernel_launch(void* const* d_in, const int* in_sizes, int n_in,
                              void* d_out, int out_size) {
    const float* x   = (const float*)d_in[0];
    const float* adj = (const float*)d_in[1];
    const float* We1 = (const float*)d_in[2];
    const float* be1 = (const float*)d_in[3];
    const float* We2 = (const float*)d_in[4];
    const float* be2 = (const float*)d_in[5];
    const float* Wl  = (const float*)d_in[6];
    const float* bl  = (const float*)d_in[7];
    const float* Wn  = (const float*)d_in[8];
    const float* bn  = (const float*)d_in[9];
    const float* Wh  = (const float*)d_in[10];
    const float* bh  = (const float*)d_in[11];
    const float* Wa  = (const float*)d_in[12];
    const float* ba  = (const float*)d_in[13];
    float* out = (float*)d_out;

    k_embed1<<<256, 256>>>(x, We1, be1);
    k_convW<<<dim3(8, 8, 4), dim3(32, 8)>>>(We2, Wn, Wh, adj);
    k_mma<0><<<dim3(8, 32), 128>>>(be2, 0);       // E2 -> E2fT
    k_mma<1><<<dim3(8, 8, 4), 128>>>(nullptr, 0); // NE -> NEf
    k_mma<2><<<dim3(8, 32), 128>>>(bn, 0);        // S_n
    k_mma<2><<<dim3(8, 32), 128>>>(bh, 1);        // S_h
    k_ah<<<16, 256>>>(x, Wl);
    k_final<<<4, 256>>>(bl, Wa, ba, out);

    (void)in_sizes; (void)n_in; (void)out_size;
}